// round 14
// baseline (speedup 1.0000x reference)
#include <cuda_runtime.h>
#include <cstdint>
#include <math.h>

#define B_SZ 8
#define C_SZ 384
#define N_TOK 1024
#define M_TOT (B_SZ * N_TOK)      // 8192
#define HEADS 8
#define HDIM 48
#define QKV_W (3 * C_SZ)          // 1152
#define STAT_BLKS (M_TOT / 64)    // 128

// ---------------- scratch ------------------------------------------------------
__device__ float g_qkv[M_TOT * QKV_W];   // [8192][1152] tf32
__device__ float g_att[M_TOT * C_SZ];    // [8192][384] attention out (fp32)
__device__ float g_wq1[QKV_W * C_SZ];    // tf32 (w_qkv * ln_w) [1152][384]
__device__ float g_wp1[C_SZ * C_SZ];     // tf32 w_proj [384][384]
__device__ float2 g_stat[M_TOT];         // per-token {r, r*mu}
__device__ float g_u[QKV_W];             // sum_k lnw_k * Wq[n][k]
__device__ float g_v[QKV_W];             // sum_k lnb_k * Wq[n][k]

// ---------------- helpers ------------------------------------------------------
__device__ __forceinline__ float fast_exp2(float x) {
    float y; asm("ex2.approx.ftz.f32 %0, %1;" : "=f"(y) : "f"(x)); return y;
}
__device__ __forceinline__ float tf32r(float x) {
    uint32_t u; asm("cvt.rna.tf32.f32 %0, %1;" : "=r"(u) : "f"(x));
    return __uint_as_float(u);
}
__device__ __forceinline__ uint32_t smem_u32(const void* p) {
    uint32_t a;
    asm("{ .reg .u64 t; cvta.to.shared.u64 t, %1; cvt.u32.u64 %0, t; }" : "=r"(a) : "l"(p));
    return a;
}
__device__ __forceinline__ void cp16(uint32_t dst, const void* src) {
    asm volatile("cp.async.cg.shared.global [%0], [%1], 16;" :: "r"(dst), "l"(src) : "memory");
}
#define CP_COMMIT() asm volatile("cp.async.commit_group;" ::: "memory")

__device__ __forceinline__ void mma_tf32(float* c, const uint32_t* a, const uint32_t* b) {
    asm volatile(
        "mma.sync.aligned.m16n8k8.row.col.f32.tf32.tf32.f32 "
        "{%0,%1,%2,%3}, {%4,%5,%6,%7}, {%8,%9}, {%0,%1,%2,%3};"
        : "+f"(c[0]), "+f"(c[1]), "+f"(c[2]), "+f"(c[3])
        : "r"(a[0]), "r"(a[1]), "r"(a[2]), "r"(a[3]), "r"(b[0]), "r"(b[1]));
}

// ---------------- fused prep: LN stats + weight prep in one launch --------------
__global__ __launch_bounds__(256) void prep_kernel(
    const float* __restrict__ x,
    const float* __restrict__ wq, const float* __restrict__ wp,
    const float* __restrict__ lnw, const float* __restrict__ lnb,
    float2* __restrict__ stat,
    float* __restrict__ wq1, float* __restrict__ wp1,
    float* __restrict__ u, float* __restrict__ v) {
    __shared__ float sred[4][64];
    __shared__ float sred2[4][64];
    int blk = blockIdx.x;
    int t = threadIdx.x;

    if (blk < STAT_BLKS) {
        int part = t >> 6;
        int tok = t & 63;
        int m = blk * 64 + tok;
        int b = m >> 10, n = m & 1023;
        const float* xb = x + ((size_t)b * C_SZ + part * 96) * N_TOK + n;
        float s = 0.f, s2 = 0.f;
        #pragma unroll 8
        for (int c = 0; c < 96; c++) {
            float vv2 = xb[(size_t)c * N_TOK];
            s += vv2; s2 += vv2 * vv2;
        }
        sred[part][tok] = s; sred2[part][tok] = s2;
        __syncthreads();
        if (part == 0) {
            s  = sred[0][tok] + sred[1][tok] + sred[2][tok] + sred[3][tok];
            s2 = sred2[0][tok] + sred2[1][tok] + sred2[2][tok] + sred2[3][tok];
            const float rC = 1.0f / C_SZ;
            float mu = s * rC;
            float var = s2 * rC - mu * mu;
            float r = rsqrtf(var + 1e-6f);
            stat[m] = make_float2(r, r * mu);
        }
    } else if (blk < STAT_BLKS + QKV_W) {
        int n = blk - STAT_BLKS;
        const float* row = wq + (size_t)n * C_SZ;
        float su = 0.f, sv = 0.f;
        for (int k = t; k < C_SZ; k += 256) {
            float pw = tf32r(row[k] * lnw[k]);
            wq1[(size_t)n * C_SZ + k] = pw;
            su += pw;
            sv += row[k] * lnb[k];
        }
        #pragma unroll
        for (int o = 16; o; o >>= 1) {
            su += __shfl_xor_sync(0xffffffffu, su, o);
            sv += __shfl_xor_sync(0xffffffffu, sv, o);
        }
        if ((t & 31) == 0) { sred[0][(t >> 5) * 2] = su; sred[0][(t >> 5) * 2 + 1] = sv; }
        __syncthreads();
        if (t == 0) {
            float tu = 0.f, tv = 0.f;
            #pragma unroll
            for (int w = 0; w < 8; w++) { tu += sred[0][w * 2]; tv += sred[0][w * 2 + 1]; }
            u[n] = tu; v[n] = tv;
        }
    } else {
        int m = blk - STAT_BLKS - QKV_W;
        for (int k = t; k < C_SZ; k += 256)
            wp1[(size_t)m * C_SZ + k] = tf32r(wp[(size_t)m * C_SZ + k]);
    }
}

// ---------------- fused LN + QKV GEMM --------------------------------------------
#define BK 16
#define LNA_ST 136
#define LNA_FL (BK * LNA_ST)          // 2176
#define SSTRIDE 20
#define LNB_FL (128 * SSTRIDE)        // 2560
#define LNSTG (LNA_FL + LNB_FL)       // 4736 floats
#define LNSMEM (4 * LNSTG * 4)        // 75776 B

__global__ __launch_bounds__(256, 2) void gemm_ln(
    const float* __restrict__ x, const float* __restrict__ Bw,
    const float2* __restrict__ stat, const float* __restrict__ uv_u,
    const float* __restrict__ uv_v, float* __restrict__ qkv) {
    extern __shared__ float sm[];
    const uint32_t usm = smem_u32(sm);
    const int tid = threadIdx.x;
    const int wid = tid >> 5, lane = tid & 31;
    const int g = lane >> 2, tig = lane & 3;
    const int m0 = blockIdx.x * 128, n0 = blockIdx.y * 128;
    const int bb = m0 >> 10, nt0 = m0 & 1023;
    const int warp_m = (wid & 3) * 32, warp_n = (wid >> 2) * 64;
    const int NSTG = C_SZ / BK;     // 24

    float acc[2][8][4];
    #pragma unroll
    for (int i = 0; i < 2; i++)
        #pragma unroll
        for (int j = 0; j < 8; j++)
            #pragma unroll
            for (int e = 0; e < 4; e++) acc[i][j][e] = 0.f;

    auto issue = [&](int s) {
        int k0 = s * BK;
        uint32_t base = usm + (uint32_t)(s & 3) * (LNSTG * 4);
        #pragma unroll
        for (int i = 0; i < 2; i++) {
            int id = tid + i * 256;
            int kr = id >> 5;
            int mc = (id & 31) * 4;
            cp16(base + (uint32_t)(kr * LNA_ST + mc) * 4,
                 x + ((size_t)bb * C_SZ + k0 + kr) * N_TOK + nt0 + mc);
        }
        #pragma unroll
        for (int i = 0; i < 2; i++) {
            int id = tid + i * 256;
            int row = id >> 2;
            int c = (id & 3) * 4;
            cp16(base + (uint32_t)(LNA_FL + row * SSTRIDE + c) * 4,
                 Bw + (size_t)(n0 + row) * C_SZ + k0 + c);
        }
    };

    issue(0); CP_COMMIT();
    issue(1); CP_COMMIT();
    issue(2); CP_COMMIT();

    for (int s = 0; s < NSTG; s++) {
        asm volatile("cp.async.wait_group 2;" ::: "memory");
        __syncthreads();
        if (s + 3 < NSTG) issue(s + 3);
        CP_COMMIT();

        const float* As = sm + (s & 3) * LNSTG;
        const float* Bs = As + LNA_FL;
        #pragma unroll
        for (int kk = 0; kk < BK; kk += 8) {
            uint32_t af[2][4], bf[8][2];
            #pragma unroll
            for (int mt = 0; mt < 2; mt++) {
                int r = warp_m + mt * 16 + g;
                af[mt][0] = __float_as_uint(As[(kk + tig) * LNA_ST + r]);
                af[mt][1] = __float_as_uint(As[(kk + tig) * LNA_ST + r + 8]);
                af[mt][2] = __float_as_uint(As[(kk + tig + 4) * LNA_ST + r]);
                af[mt][3] = __float_as_uint(As[(kk + tig + 4) * LNA_ST + r + 8]);
            }
            #pragma unroll
            for (int nt = 0; nt < 8; nt++) {
                int r = warp_n + nt * 8 + g;
                bf[nt][0] = __float_as_uint(Bs[r * SSTRIDE + kk + tig]);
                bf[nt][1] = __float_as_uint(Bs[r * SSTRIDE + kk + tig + 4]);
            }
            #pragma unroll
            for (int mt = 0; mt < 2; mt++)
                #pragma unroll
                for (int nt = 0; nt < 8; nt++)
                    mma_tf32(acc[mt][nt], af[mt], bf[nt]);
        }
    }

    #pragma unroll
    for (int mt = 0; mt < 2; mt++) {
        int row = m0 + warp_m + mt * 16 + g;
        float2 s0 = stat[row];
        float2 s1 = stat[row + 8];
        #pragma unroll
        for (int nt = 0; nt < 8; nt++) {
            int col = n0 + warp_n + nt * 8 + tig * 2;
            float2 uu = *(const float2*)&uv_u[col];
            float2 vv = *(const float2*)&uv_v[col];
            float* c = acc[mt][nt];
            float o0 = s0.x * c[0] - s0.y * uu.x + vv.x;
            float o1 = s0.x * c[1] - s0.y * uu.y + vv.y;
            float o2 = s1.x * c[2] - s1.y * uu.x + vv.x;
            float o3 = s1.x * c[3] - s1.y * uu.y + vv.y;
            *(float2*)&qkv[(size_t)row * QKV_W + col] = make_float2(tf32r(o0), tf32r(o1));
            *(float2*)&qkv[(size_t)(row + 8) * QKV_W + col] = make_float2(tf32r(o2), tf32r(o3));
        }
    }
}

// ---------------- proj GEMM: out[b][cout][n] = resid + wp1 . att^T ---------------
// 128 threads / 4 warps, warp tile 32x64 (2m x 2n warps over 64x128 CTA tile).
// 16 MMAs per k-half per warp: 2x ILP and 2x MMA-per-LDS vs the old 32x32 tile.
#define PA_FL (64 * SSTRIDE)          // 1280
#define PB_FL (128 * SSTRIDE)         // 2560
#define PSTG (PA_FL + PB_FL)          // 3840 floats
#define PSMEM (4 * PSTG * 4)          // 61440 B

__global__ __launch_bounds__(128, 3) void gemm_proj(
    const float* __restrict__ A, const float* __restrict__ Bw,
    float* __restrict__ Cout, const float* __restrict__ resid) {
    extern __shared__ float sm[];
    const uint32_t usm = smem_u32(sm);
    const int tid = threadIdx.x;
    const int wid = tid >> 5, lane = tid & 31;
    const int g = lane >> 2, tig = lane & 3;
    const int m0 = blockIdx.x * 64, n0 = blockIdx.y * 128;
    const int warp_m = (wid & 1) * 32, warp_n = (wid >> 1) * 64;
    const int NSTG = C_SZ / BK;

    float acc[2][8][4];
    #pragma unroll
    for (int i = 0; i < 2; i++)
        #pragma unroll
        for (int j = 0; j < 8; j++)
            #pragma unroll
            for (int e = 0; e < 4; e++) acc[i][j][e] = 0.f;

    auto issue = [&](int s) {
        int k0 = s * BK;
        uint32_t base = usm + (uint32_t)(s & 3) * (PSTG * 4);
        // A: 64 rows x 16 floats = 256 cp16, 128 threads -> 2 iters
        #pragma unroll
        for (int i = 0; i < 2; i++) {
            int id = tid + i * 128;
            int row = id >> 2, c = (id & 3) * 4;
            cp16(base + (uint32_t)(row * SSTRIDE + c) * 4,
                 A + (size_t)(m0 + row) * C_SZ + k0 + c);
        }
        // B: 128 rows x 16 floats = 512 cp16, 4 iters
        #pragma unroll
        for (int i = 0; i < 4; i++) {
            int id = tid + i * 128;
            int row = id >> 2, c = (id & 3) * 4;
            cp16(base + (uint32_t)(PA_FL + row * SSTRIDE + c) * 4,
                 Bw + (size_t)(n0 + row) * C_SZ + k0 + c);
        }
    };

    issue(0); CP_COMMIT();
    issue(1); CP_COMMIT();
    issue(2); CP_COMMIT();

    for (int s = 0; s < NSTG; s++) {
        asm volatile("cp.async.wait_group 2;" ::: "memory");
        __syncthreads();
        if (s + 3 < NSTG) issue(s + 3);
        CP_COMMIT();

        const float* As = sm + (s & 3) * PSTG;
        const float* Bs = As + PA_FL;
        #pragma unroll
        for (int kk = 0; kk < BK; kk += 8) {
            uint32_t af[2][4], bf[8][2];
            #pragma unroll
            for (int mt = 0; mt < 2; mt++) {
                int r = warp_m + mt * 16 + g;
                af[mt][0] = __float_as_uint(As[(r    ) * SSTRIDE + kk + tig]);
                af[mt][1] = __float_as_uint(As[(r + 8) * SSTRIDE + kk + tig]);
                af[mt][2] = __float_as_uint(As[(r    ) * SSTRIDE + kk + tig + 4]);
                af[mt][3] = __float_as_uint(As[(r + 8) * SSTRIDE + kk + tig + 4]);
            }
            #pragma unroll
            for (int nt = 0; nt < 8; nt++) {
                int r = warp_n + nt * 8 + g;
                bf[nt][0] = __float_as_uint(Bs[r * SSTRIDE + kk + tig]);
                bf[nt][1] = __float_as_uint(Bs[r * SSTRIDE + kk + tig + 4]);
            }
            #pragma unroll
            for (int mt = 0; mt < 2; mt++)
                #pragma unroll
                for (int nt = 0; nt < 8; nt++)
                    mma_tf32(acc[mt][nt], af[mt], bf[nt]);
        }
    }

    #pragma unroll
    for (int mt = 0; mt < 2; mt++) {
        int row = m0 + warp_m + mt * 16 + g;
        #pragma unroll
        for (int nt = 0; nt < 8; nt++) {
            int col = n0 + warp_n + nt * 8 + tig * 2;
            int bb = col >> 10, tok = col & 1023;
            float* c = acc[mt][nt];
            size_t i0 = ((size_t)bb * C_SZ + row) * N_TOK + tok;
            size_t i1 = ((size_t)bb * C_SZ + row + 8) * N_TOK + tok;
            float2 r0 = *(const float2*)&resid[i0];
            float2 r1 = *(const float2*)&resid[i1];
            *(float2*)&Cout[i0] = make_float2(r0.x + c[0], r0.y + c[1]);
            *(float2*)&Cout[i1] = make_float2(r1.x + c[2], r1.y + c[3]);
        }
    }
}

// ---------------- tensor-core flash attention (BC=128, 2 passes per load) --------
#define BC 128
#define KSTRIDE 52
#define VSTRIDE 56
#define KST (BC * KSTRIDE)
#define VST (BC * VSTRIDE)
#define ABUF (KST + VST)
#define ASMEM (2 * ABUF * 4)     // 110592 bytes

__global__ __launch_bounds__(128, 2) void attn_mma(
    const float* __restrict__ qkv, float* __restrict__ att) {
    extern __shared__ float sm[];
    const uint32_t usm = smem_u32(sm);
    const int tid = threadIdx.x;
    const int wid = tid >> 5, lane = tid & 31;
    const int g = lane >> 2, tig = lane & 3;
    const int bh = blockIdx.y;
    const int b = bh >> 3, h = bh & 7;
    const int q0 = blockIdx.x * 128 + wid * 32;
    const float QS = 0.14433756729740643f * 1.44269504088896340f;
    const int gperm = (g >> 1) + (g & 1) * 4;    // sigma(g)

    uint32_t qa[2][6][4];
    {
        const float* Qb = qkv + ((size_t)(b * N_TOK + q0)) * QKV_W + h * HDIM;
        #pragma unroll
        for (int mt = 0; mt < 2; mt++) {
            const float* Qm = Qb + (size_t)(mt * 16) * QKV_W;
            #pragma unroll
            for (int kk = 0; kk < 6; kk++) {
                qa[mt][kk][0] = __float_as_uint(tf32r(Qm[(size_t)g * QKV_W + kk*8 + tig] * QS));
                qa[mt][kk][1] = __float_as_uint(tf32r(Qm[(size_t)(g+8) * QKV_W + kk*8 + tig] * QS));
                qa[mt][kk][2] = __float_as_uint(tf32r(Qm[(size_t)g * QKV_W + kk*8 + tig + 4] * QS));
                qa[mt][kk][3] = __float_as_uint(tf32r(Qm[(size_t)(g+8) * QKV_W + kk*8 + tig + 4] * QS));
            }
        }
    }

    float o[2][6][4];
    #pragma unroll
    for (int mt = 0; mt < 2; mt++)
        #pragma unroll
        for (int nt = 0; nt < 6; nt++)
            #pragma unroll
            for (int e = 0; e < 4; e++) o[mt][nt][e] = 0.f;
    float ps[2][2] = {{0.f, 0.f}, {0.f, 0.f}};

    auto issue = [&](int t) {
        int j0 = t * BC;
        uint32_t base = usm + (uint32_t)(t & 1) * (ABUF * 4);
        const float* kb = qkv + ((size_t)(b * N_TOK + j0)) * QKV_W + C_SZ + h * HDIM;
        const float* vb = kb + C_SZ;
        #pragma unroll
        for (int i = 0; i < 12; i++) {
            int id = tid + i * 128;
            int r = id / 12, c = (id % 12) * 4;
            cp16(base + (uint32_t)(r * KSTRIDE + c) * 4, kb + (size_t)r * QKV_W + c);
            cp16(base + (uint32_t)(KST + r * VSTRIDE + c) * 4, vb + (size_t)r * QKV_W + c);
        }
    };

    issue(0); CP_COMMIT();

    for (int t = 0; t < N_TOK / BC; t++) {
        asm volatile("cp.async.wait_group 0;" ::: "memory");
        __syncthreads();
        if (t + 1 < N_TOK / BC) issue(t + 1);
        CP_COMMIT();

        #pragma unroll
        for (int pass = 0; pass < 2; pass++) {
            const float* ks = sm + (t & 1) * ABUF + pass * 64 * KSTRIDE;
            const float* vs = sm + (t & 1) * ABUF + KST + pass * 64 * VSTRIDE;

            float sc[2][8][4];
            #pragma unroll
            for (int mt = 0; mt < 2; mt++)
                #pragma unroll
                for (int nt = 0; nt < 8; nt++)
                    #pragma unroll
                    for (int e = 0; e < 4; e++) sc[mt][nt][e] = 0.f;
            #pragma unroll
            for (int kk = 0; kk < 6; kk++) {
                #pragma unroll
                for (int nt = 0; nt < 8; nt++) {
                    uint32_t bf[2];
                    bf[0] = __float_as_uint(ks[(nt*8 + gperm) * KSTRIDE + kk*8 + tig]);
                    bf[1] = __float_as_uint(ks[(nt*8 + gperm) * KSTRIDE + kk*8 + tig + 4]);
                    mma_tf32(sc[0][nt], qa[0][kk], bf);
                    mma_tf32(sc[1][nt], qa[1][kk], bf);
                }
            }

            #pragma unroll
            for (int mt = 0; mt < 2; mt++) {
                #pragma unroll
                for (int nt = 0; nt < 8; nt++) {
                    sc[mt][nt][0] = fast_exp2(sc[mt][nt][0]);
                    sc[mt][nt][1] = fast_exp2(sc[mt][nt][1]);
                    sc[mt][nt][2] = fast_exp2(sc[mt][nt][2]);
                    sc[mt][nt][3] = fast_exp2(sc[mt][nt][3]);
                    ps[mt][0] += sc[mt][nt][0] + sc[mt][nt][1];
                    ps[mt][1] += sc[mt][nt][2] + sc[mt][nt][3];
                }
            }

            #pragma unroll
            for (int kt = 0; kt < 8; kt++) {
                uint32_t pa[2][4];
                #pragma unroll
                for (int mt = 0; mt < 2; mt++) {
                    pa[mt][0] = __float_as_uint(sc[mt][kt][0]);
                    pa[mt][1] = __float_as_uint(sc[mt][kt][2]);
                    pa[mt][2] = __float_as_uint(sc[mt][kt][1]);
                    pa[mt][3] = __float_as_uint(sc[mt][kt][3]);
                }
                #pragma unroll
                for (int nt = 0; nt < 6; nt++) {
                    uint32_t bf[2];
                    bf[0] = __float_as_uint(vs[(kt*8 + tig) * VSTRIDE + nt*8 + g]);
                    bf[1] = __float_as_uint(vs[(kt*8 + tig + 4) * VSTRIDE + nt*8 + g]);
                    mma_tf32(o[0][nt], pa[0], bf);
                    mma_tf32(o[1][nt], pa[1], bf);
                }
            }
        }
    }

    #pragma unroll
    for (int mt = 0; mt < 2; mt++) {
        float l0 = ps[mt][0], l1 = ps[mt][1];
        l0 += __shfl_xor_sync(0xffffffffu, l0, 1);
        l0 += __shfl_xor_sync(0xffffffffu, l0, 2);
        l1 += __shfl_xor_sync(0xffffffffu, l1, 1);
        l1 += __shfl_xor_sync(0xffffffffu, l1, 2);
        float inv0 = 1.f / l0, inv1 = 1.f / l1;
        float* or0 = att + ((size_t)(b * N_TOK + q0 + mt * 16 + g)) * C_SZ + h * HDIM;
        float* or1 = or0 + (size_t)8 * C_SZ;
        #pragma unroll
        for (int nt = 0; nt < 6; nt++) {
            *(float2*)&or0[nt*8 + tig*2] =
                make_float2(o[mt][nt][0] * inv0, o[mt][nt][1] * inv0);
            *(float2*)&or1[nt*8 + tig*2] =
                make_float2(o[mt][nt][2] * inv1, o[mt][nt][3] * inv1);
        }
    }
}

// ---------------- launch --------------------------------------------------------
extern "C" void kernel_launch(void* const* d_in, const int* in_sizes, int n_in,
                              void* d_out, int out_size) {
    const float* x      = (const float*)d_in[0];
    const float* w_qkv  = (const float*)d_in[1];
    const float* w_proj = (const float*)d_in[2];
    const float* ln_w   = (const float*)d_in[3];
    const float* ln_b   = (const float*)d_in[4];
    float* out = (float*)d_out;

    float *qkv, *att, *wq1, *wp1, *uu, *vv;
    float2* stat;
    cudaGetSymbolAddress((void**)&qkv,  g_qkv);
    cudaGetSymbolAddress((void**)&att,  g_att);
    cudaGetSymbolAddress((void**)&wq1,  g_wq1);
    cudaGetSymbolAddress((void**)&wp1,  g_wp1);
    cudaGetSymbolAddress((void**)&stat, g_stat);
    cudaGetSymbolAddress((void**)&uu,   g_u);
    cudaGetSymbolAddress((void**)&vv,   g_v);

    cudaFuncSetAttribute(gemm_ln, cudaFuncAttributeMaxDynamicSharedMemorySize, LNSMEM);
    cudaFuncSetAttribute(gemm_proj, cudaFuncAttributeMaxDynamicSharedMemorySize, PSMEM);
    cudaFuncSetAttribute(attn_mma, cudaFuncAttributeMaxDynamicSharedMemorySize, ASMEM);

    // 1) fused prep: LN stats + weight prep (single launch)
    prep_kernel<<<STAT_BLKS + QKV_W + C_SZ, 256>>>(x, w_qkv, w_proj, ln_w, ln_b,
                                                   stat, wq1, wp1, uu, vv);

    // 2) fused LN + QKV GEMM: [8192 x 1152]
    gemm_ln<<<dim3(M_TOT / 128, QKV_W / 128), 256, LNSMEM>>>(x, wq1, stat, uu, vv, qkv);

    // 3) attention -> att [8192][384]
    attn_mma<<<dim3(N_TOK / 128, B_SZ * HEADS), 128, ASMEM>>>(qkv, att);

    // 4) proj GEMM + residual -> out [B][C][H][W]
    gemm_proj<<<dim3(C_SZ / 64, M_TOT / 128), 128, PSMEM>>>(wp1, att, out, x);
}

// round 15
// speedup vs baseline: 1.2916x; 1.2916x over previous
#include <cuda_runtime.h>
#include <cstdint>
#include <math.h>

#define B_SZ 8
#define C_SZ 384
#define N_TOK 1024
#define M_TOT (B_SZ * N_TOK)      // 8192
#define HEADS 8
#define HDIM 48
#define QKV_W (3 * C_SZ)          // 1152
#define STAT_BLKS (M_TOT / 64)    // 128

// ---------------- scratch ------------------------------------------------------
__device__ float g_qkv[M_TOT * QKV_W];   // [8192][1152] tf32
__device__ float g_att[M_TOT * C_SZ];    // [8192][384] attention out (fp32)
__device__ float g_wq1[QKV_W * C_SZ];    // tf32 (w_qkv * ln_w) [1152][384]
__device__ float g_wp1[C_SZ * C_SZ];     // tf32 w_proj [384][384]
__device__ float2 g_stat[M_TOT];         // per-token {r, r*mu}
__device__ float g_u[QKV_W];             // sum_k lnw_k * Wq[n][k]
__device__ float g_v[QKV_W];             // sum_k lnb_k * Wq[n][k]

// ---------------- helpers ------------------------------------------------------
__device__ __forceinline__ float fast_exp2(float x) {
    float y; asm("ex2.approx.ftz.f32 %0, %1;" : "=f"(y) : "f"(x)); return y;
}
__device__ __forceinline__ float tf32r(float x) {
    uint32_t u; asm("cvt.rna.tf32.f32 %0, %1;" : "=r"(u) : "f"(x));
    return __uint_as_float(u);
}
__device__ __forceinline__ uint32_t smem_u32(const void* p) {
    uint32_t a;
    asm("{ .reg .u64 t; cvta.to.shared.u64 t, %1; cvt.u32.u64 %0, t; }" : "=r"(a) : "l"(p));
    return a;
}
__device__ __forceinline__ void cp16(uint32_t dst, const void* src) {
    asm volatile("cp.async.cg.shared.global [%0], [%1], 16;" :: "r"(dst), "l"(src) : "memory");
}
#define CP_COMMIT() asm volatile("cp.async.commit_group;" ::: "memory")

__device__ __forceinline__ void mma_tf32(float* c, const uint32_t* a, const uint32_t* b) {
    asm volatile(
        "mma.sync.aligned.m16n8k8.row.col.f32.tf32.tf32.f32 "
        "{%0,%1,%2,%3}, {%4,%5,%6,%7}, {%8,%9}, {%0,%1,%2,%3};"
        : "+f"(c[0]), "+f"(c[1]), "+f"(c[2]), "+f"(c[3])
        : "r"(a[0]), "r"(a[1]), "r"(a[2]), "r"(a[3]), "r"(b[0]), "r"(b[1]));
}

// ---------------- fused prep: LN stats + weight prep in one launch --------------
__global__ __launch_bounds__(256) void prep_kernel(
    const float* __restrict__ x,
    const float* __restrict__ wq, const float* __restrict__ wp,
    const float* __restrict__ lnw, const float* __restrict__ lnb,
    float2* __restrict__ stat,
    float* __restrict__ wq1, float* __restrict__ wp1,
    float* __restrict__ u, float* __restrict__ v) {
    __shared__ float sred[4][64];
    __shared__ float sred2[4][64];
    int blk = blockIdx.x;
    int t = threadIdx.x;

    if (blk < STAT_BLKS) {
        int part = t >> 6;
        int tok = t & 63;
        int m = blk * 64 + tok;
        int b = m >> 10, n = m & 1023;
        const float* xb = x + ((size_t)b * C_SZ + part * 96) * N_TOK + n;
        float s = 0.f, s2 = 0.f;
        #pragma unroll 8
        for (int c = 0; c < 96; c++) {
            float vv2 = xb[(size_t)c * N_TOK];
            s += vv2; s2 += vv2 * vv2;
        }
        sred[part][tok] = s; sred2[part][tok] = s2;
        __syncthreads();
        if (part == 0) {
            s  = sred[0][tok] + sred[1][tok] + sred[2][tok] + sred[3][tok];
            s2 = sred2[0][tok] + sred2[1][tok] + sred2[2][tok] + sred2[3][tok];
            const float rC = 1.0f / C_SZ;
            float mu = s * rC;
            float var = s2 * rC - mu * mu;
            float r = rsqrtf(var + 1e-6f);
            stat[m] = make_float2(r, r * mu);
        }
    } else if (blk < STAT_BLKS + QKV_W) {
        int n = blk - STAT_BLKS;
        const float* row = wq + (size_t)n * C_SZ;
        float su = 0.f, sv = 0.f;
        for (int k = t; k < C_SZ; k += 256) {
            float pw = tf32r(row[k] * lnw[k]);
            wq1[(size_t)n * C_SZ + k] = pw;
            su += pw;
            sv += row[k] * lnb[k];
        }
        #pragma unroll
        for (int o = 16; o; o >>= 1) {
            su += __shfl_xor_sync(0xffffffffu, su, o);
            sv += __shfl_xor_sync(0xffffffffu, sv, o);
        }
        if ((t & 31) == 0) { sred[0][(t >> 5) * 2] = su; sred[0][(t >> 5) * 2 + 1] = sv; }
        __syncthreads();
        if (t == 0) {
            float tu = 0.f, tv = 0.f;
            #pragma unroll
            for (int w = 0; w < 8; w++) { tu += sred[0][w * 2]; tv += sred[0][w * 2 + 1]; }
            u[n] = tu; v[n] = tv;
        }
    } else {
        int m = blk - STAT_BLKS - QKV_W;
        for (int k = t; k < C_SZ; k += 256)
            wp1[(size_t)m * C_SZ + k] = tf32r(wp[(size_t)m * C_SZ + k]);
    }
}

// ---------------- fused LN + QKV GEMM --------------------------------------------
#define BK 16
#define LNA_ST 136
#define LNA_FL (BK * LNA_ST)          // 2176
#define SSTRIDE 20
#define LNB_FL (128 * SSTRIDE)        // 2560
#define LNSTG (LNA_FL + LNB_FL)       // 4736 floats
#define LNSMEM (4 * LNSTG * 4)        // 75776 B

__global__ __launch_bounds__(256, 2) void gemm_ln(
    const float* __restrict__ x, const float* __restrict__ Bw,
    const float2* __restrict__ stat, const float* __restrict__ uv_u,
    const float* __restrict__ uv_v, float* __restrict__ qkv) {
    extern __shared__ float sm[];
    const uint32_t usm = smem_u32(sm);
    const int tid = threadIdx.x;
    const int wid = tid >> 5, lane = tid & 31;
    const int g = lane >> 2, tig = lane & 3;
    const int m0 = blockIdx.x * 128, n0 = blockIdx.y * 128;
    const int bb = m0 >> 10, nt0 = m0 & 1023;
    const int warp_m = (wid & 3) * 32, warp_n = (wid >> 2) * 64;
    const int NSTG = C_SZ / BK;     // 24

    float acc[2][8][4];
    #pragma unroll
    for (int i = 0; i < 2; i++)
        #pragma unroll
        for (int j = 0; j < 8; j++)
            #pragma unroll
            for (int e = 0; e < 4; e++) acc[i][j][e] = 0.f;

    auto issue = [&](int s) {
        int k0 = s * BK;
        uint32_t base = usm + (uint32_t)(s & 3) * (LNSTG * 4);
        #pragma unroll
        for (int i = 0; i < 2; i++) {
            int id = tid + i * 256;
            int kr = id >> 5;
            int mc = (id & 31) * 4;
            cp16(base + (uint32_t)(kr * LNA_ST + mc) * 4,
                 x + ((size_t)bb * C_SZ + k0 + kr) * N_TOK + nt0 + mc);
        }
        #pragma unroll
        for (int i = 0; i < 2; i++) {
            int id = tid + i * 256;
            int row = id >> 2;
            int c = (id & 3) * 4;
            cp16(base + (uint32_t)(LNA_FL + row * SSTRIDE + c) * 4,
                 Bw + (size_t)(n0 + row) * C_SZ + k0 + c);
        }
    };

    issue(0); CP_COMMIT();
    issue(1); CP_COMMIT();
    issue(2); CP_COMMIT();

    for (int s = 0; s < NSTG; s++) {
        asm volatile("cp.async.wait_group 2;" ::: "memory");
        __syncthreads();
        if (s + 3 < NSTG) issue(s + 3);
        CP_COMMIT();

        const float* As = sm + (s & 3) * LNSTG;
        const float* Bs = As + LNA_FL;
        #pragma unroll
        for (int kk = 0; kk < BK; kk += 8) {
            uint32_t af[2][4], bf[8][2];
            #pragma unroll
            for (int mt = 0; mt < 2; mt++) {
                int r = warp_m + mt * 16 + g;
                af[mt][0] = __float_as_uint(As[(kk + tig) * LNA_ST + r]);
                af[mt][1] = __float_as_uint(As[(kk + tig) * LNA_ST + r + 8]);
                af[mt][2] = __float_as_uint(As[(kk + tig + 4) * LNA_ST + r]);
                af[mt][3] = __float_as_uint(As[(kk + tig + 4) * LNA_ST + r + 8]);
            }
            #pragma unroll
            for (int nt = 0; nt < 8; nt++) {
                int r = warp_n + nt * 8 + g;
                bf[nt][0] = __float_as_uint(Bs[r * SSTRIDE + kk + tig]);
                bf[nt][1] = __float_as_uint(Bs[r * SSTRIDE + kk + tig + 4]);
            }
            #pragma unroll
            for (int mt = 0; mt < 2; mt++)
                #pragma unroll
                for (int nt = 0; nt < 8; nt++)
                    mma_tf32(acc[mt][nt], af[mt], bf[nt]);
        }
    }

    #pragma unroll
    for (int mt = 0; mt < 2; mt++) {
        int row = m0 + warp_m + mt * 16 + g;
        float2 s0 = stat[row];
        float2 s1 = stat[row + 8];
        #pragma unroll
        for (int nt = 0; nt < 8; nt++) {
            int col = n0 + warp_n + nt * 8 + tig * 2;
            float2 uu = *(const float2*)&uv_u[col];
            float2 vv = *(const float2*)&uv_v[col];
            float* c = acc[mt][nt];
            float o0 = s0.x * c[0] - s0.y * uu.x + vv.x;
            float o1 = s0.x * c[1] - s0.y * uu.y + vv.y;
            float o2 = s1.x * c[2] - s1.y * uu.x + vv.x;
            float o3 = s1.x * c[3] - s1.y * uu.y + vv.y;
            *(float2*)&qkv[(size_t)row * QKV_W + col] = make_float2(tf32r(o0), tf32r(o1));
            *(float2*)&qkv[(size_t)(row + 8) * QKV_W + col] = make_float2(tf32r(o2), tf32r(o3));
        }
    }
}

// ---------------- proj GEMM: out[b][cout][n] = resid + wp1 . att^T ---------------
// R13 shape (256 threads, 8 warps, warp tile 32x32) but BK=32: 12 stages
// instead of 24 -> half the wait/sync boundaries, 2x MMA chain per stage.
// Stride 36: fragment gather bank = (4r + tig) mod 32 covers all banks.
#define PBK 32
#define PSTR 36
#define PA_FL (64 * PSTR)             // 2304 floats
#define PB_FL (128 * PSTR)            // 4608 floats
#define PSTG (PA_FL + PB_FL)          // 6912 floats
#define PSMEM (4 * PSTG * 4)          // 110592 B

__global__ __launch_bounds__(256, 2) void gemm_proj(
    const float* __restrict__ A, const float* __restrict__ Bw,
    float* __restrict__ Cout, const float* __restrict__ resid) {
    extern __shared__ float sm[];
    const uint32_t usm = smem_u32(sm);
    const int tid = threadIdx.x;
    const int wid = tid >> 5, lane = tid & 31;
    const int g = lane >> 2, tig = lane & 3;
    const int m0 = blockIdx.x * 64, n0 = blockIdx.y * 128;
    const int warp_m = (wid & 1) * 32, warp_n = (wid >> 1) * 32;
    const int NSTG = C_SZ / PBK;      // 12

    float acc[2][4][4];
    #pragma unroll
    for (int i = 0; i < 2; i++)
        #pragma unroll
        for (int j = 0; j < 4; j++)
            #pragma unroll
            for (int e = 0; e < 4; e++) acc[i][j][e] = 0.f;

    auto issue = [&](int s) {
        int k0 = s * PBK;
        uint32_t base = usm + (uint32_t)(s & 3) * (PSTG * 4);
        // A: 64 rows x 32 floats = 512 cp16; 256 thr -> 2 iters
        #pragma unroll
        for (int i = 0; i < 2; i++) {
            int id = tid + i * 256;
            int row = id >> 3, c = (id & 7) * 4;
            cp16(base + (uint32_t)(row * PSTR + c) * 4,
                 A + (size_t)(m0 + row) * C_SZ + k0 + c);
        }
        // B: 128 rows x 32 floats = 1024 cp16; 4 iters
        #pragma unroll
        for (int i = 0; i < 4; i++) {
            int id = tid + i * 256;
            int row = id >> 3, c = (id & 7) * 4;
            cp16(base + (uint32_t)(PA_FL + row * PSTR + c) * 4,
                 Bw + (size_t)(n0 + row) * C_SZ + k0 + c);
        }
    };

    issue(0); CP_COMMIT();
    issue(1); CP_COMMIT();
    issue(2); CP_COMMIT();

    for (int s = 0; s < NSTG; s++) {
        asm volatile("cp.async.wait_group 2;" ::: "memory");
        __syncthreads();
        if (s + 3 < NSTG) issue(s + 3);
        CP_COMMIT();

        const float* As = sm + (s & 3) * PSTG;
        const float* Bs = As + PA_FL;
        #pragma unroll
        for (int kk = 0; kk < PBK; kk += 8) {
            uint32_t af[2][4], bf[4][2];
            #pragma unroll
            for (int mt = 0; mt < 2; mt++) {
                int r = warp_m + mt * 16 + g;
                af[mt][0] = __float_as_uint(As[(r    ) * PSTR + kk + tig]);
                af[mt][1] = __float_as_uint(As[(r + 8) * PSTR + kk + tig]);
                af[mt][2] = __float_as_uint(As[(r    ) * PSTR + kk + tig + 4]);
                af[mt][3] = __float_as_uint(As[(r + 8) * PSTR + kk + tig + 4]);
            }
            #pragma unroll
            for (int nt = 0; nt < 4; nt++) {
                int r = warp_n + nt * 8 + g;
                bf[nt][0] = __float_as_uint(Bs[r * PSTR + kk + tig]);
                bf[nt][1] = __float_as_uint(Bs[r * PSTR + kk + tig + 4]);
            }
            #pragma unroll
            for (int mt = 0; mt < 2; mt++)
                #pragma unroll
                for (int nt = 0; nt < 4; nt++)
                    mma_tf32(acc[mt][nt], af[mt], bf[nt]);
        }
    }

    #pragma unroll
    for (int mt = 0; mt < 2; mt++) {
        int row = m0 + warp_m + mt * 16 + g;
        #pragma unroll
        for (int nt = 0; nt < 4; nt++) {
            int col = n0 + warp_n + nt * 8 + tig * 2;
            int bb = col >> 10, tok = col & 1023;
            float* c = acc[mt][nt];
            size_t i0 = ((size_t)bb * C_SZ + row) * N_TOK + tok;
            size_t i1 = ((size_t)bb * C_SZ + row + 8) * N_TOK + tok;
            float2 r0 = *(const float2*)&resid[i0];
            float2 r1 = *(const float2*)&resid[i1];
            *(float2*)&Cout[i0] = make_float2(r0.x + c[0], r0.y + c[1]);
            *(float2*)&Cout[i1] = make_float2(r1.x + c[2], r1.y + c[3]);
        }
    }
}

// ---------------- tensor-core flash attention (BC=128, 2 passes per load) --------
#define BC 128
#define KSTRIDE 52
#define VSTRIDE 56
#define KST (BC * KSTRIDE)
#define VST (BC * VSTRIDE)
#define ABUF (KST + VST)
#define ASMEM (2 * ABUF * 4)     // 110592 bytes

__global__ __launch_bounds__(128, 2) void attn_mma(
    const float* __restrict__ qkv, float* __restrict__ att) {
    extern __shared__ float sm[];
    const uint32_t usm = smem_u32(sm);
    const int tid = threadIdx.x;
    const int wid = tid >> 5, lane = tid & 31;
    const int g = lane >> 2, tig = lane & 3;
    const int bh = blockIdx.y;
    const int b = bh >> 3, h = bh & 7;
    const int q0 = blockIdx.x * 128 + wid * 32;
    const float QS = 0.14433756729740643f * 1.44269504088896340f;
    const int gperm = (g >> 1) + (g & 1) * 4;    // sigma(g)

    uint32_t qa[2][6][4];
    {
        const float* Qb = qkv + ((size_t)(b * N_TOK + q0)) * QKV_W + h * HDIM;
        #pragma unroll
        for (int mt = 0; mt < 2; mt++) {
            const float* Qm = Qb + (size_t)(mt * 16) * QKV_W;
            #pragma unroll
            for (int kk = 0; kk < 6; kk++) {
                qa[mt][kk][0] = __float_as_uint(tf32r(Qm[(size_t)g * QKV_W + kk*8 + tig] * QS));
                qa[mt][kk][1] = __float_as_uint(tf32r(Qm[(size_t)(g+8) * QKV_W + kk*8 + tig] * QS));
                qa[mt][kk][2] = __float_as_uint(tf32r(Qm[(size_t)g * QKV_W + kk*8 + tig + 4] * QS));
                qa[mt][kk][3] = __float_as_uint(tf32r(Qm[(size_t)(g+8) * QKV_W + kk*8 + tig + 4] * QS));
            }
        }
    }

    float o[2][6][4];
    #pragma unroll
    for (int mt = 0; mt < 2; mt++)
        #pragma unroll
        for (int nt = 0; nt < 6; nt++)
            #pragma unroll
            for (int e = 0; e < 4; e++) o[mt][nt][e] = 0.f;
    float ps[2][2] = {{0.f, 0.f}, {0.f, 0.f}};

    auto issue = [&](int t) {
        int j0 = t * BC;
        uint32_t base = usm + (uint32_t)(t & 1) * (ABUF * 4);
        const float* kb = qkv + ((size_t)(b * N_TOK + j0)) * QKV_W + C_SZ + h * HDIM;
        const float* vb = kb + C_SZ;
        #pragma unroll
        for (int i = 0; i < 12; i++) {
            int id = tid + i * 128;
            int r = id / 12, c = (id % 12) * 4;
            cp16(base + (uint32_t)(r * KSTRIDE + c) * 4, kb + (size_t)r * QKV_W + c);
            cp16(base + (uint32_t)(KST + r * VSTRIDE + c) * 4, vb + (size_t)r * QKV_W + c);
        }
    };

    issue(0); CP_COMMIT();

    for (int t = 0; t < N_TOK / BC; t++) {
        asm volatile("cp.async.wait_group 0;" ::: "memory");
        __syncthreads();
        if (t + 1 < N_TOK / BC) issue(t + 1);
        CP_COMMIT();

        #pragma unroll
        for (int pass = 0; pass < 2; pass++) {
            const float* ks = sm + (t & 1) * ABUF + pass * 64 * KSTRIDE;
            const float* vs = sm + (t & 1) * ABUF + KST + pass * 64 * VSTRIDE;

            float sc[2][8][4];
            #pragma unroll
            for (int mt = 0; mt < 2; mt++)
                #pragma unroll
                for (int nt = 0; nt < 8; nt++)
                    #pragma unroll
                    for (int e = 0; e < 4; e++) sc[mt][nt][e] = 0.f;
            #pragma unroll
            for (int kk = 0; kk < 6; kk++) {
                #pragma unroll
                for (int nt = 0; nt < 8; nt++) {
                    uint32_t bf[2];
                    bf[0] = __float_as_uint(ks[(nt*8 + gperm) * KSTRIDE + kk*8 + tig]);
                    bf[1] = __float_as_uint(ks[(nt*8 + gperm) * KSTRIDE + kk*8 + tig + 4]);
                    mma_tf32(sc[0][nt], qa[0][kk], bf);
                    mma_tf32(sc[1][nt], qa[1][kk], bf);
                }
            }

            #pragma unroll
            for (int mt = 0; mt < 2; mt++) {
                #pragma unroll
                for (int nt = 0; nt < 8; nt++) {
                    sc[mt][nt][0] = fast_exp2(sc[mt][nt][0]);
                    sc[mt][nt][1] = fast_exp2(sc[mt][nt][1]);
                    sc[mt][nt][2] = fast_exp2(sc[mt][nt][2]);
                    sc[mt][nt][3] = fast_exp2(sc[mt][nt][3]);
                    ps[mt][0] += sc[mt][nt][0] + sc[mt][nt][1];
                    ps[mt][1] += sc[mt][nt][2] + sc[mt][nt][3];
                }
            }

            #pragma unroll
            for (int kt = 0; kt < 8; kt++) {
                uint32_t pa[2][4];
                #pragma unroll
                for (int mt = 0; mt < 2; mt++) {
                    pa[mt][0] = __float_as_uint(sc[mt][kt][0]);
                    pa[mt][1] = __float_as_uint(sc[mt][kt][2]);
                    pa[mt][2] = __float_as_uint(sc[mt][kt][1]);
                    pa[mt][3] = __float_as_uint(sc[mt][kt][3]);
                }
                #pragma unroll
                for (int nt = 0; nt < 6; nt++) {
                    uint32_t bf[2];
                    bf[0] = __float_as_uint(vs[(kt*8 + tig) * VSTRIDE + nt*8 + g]);
                    bf[1] = __float_as_uint(vs[(kt*8 + tig + 4) * VSTRIDE + nt*8 + g]);
                    mma_tf32(o[0][nt], pa[0], bf);
                    mma_tf32(o[1][nt], pa[1], bf);
                }
            }
        }
    }

    #pragma unroll
    for (int mt = 0; mt < 2; mt++) {
        float l0 = ps[mt][0], l1 = ps[mt][1];
        l0 += __shfl_xor_sync(0xffffffffu, l0, 1);
        l0 += __shfl_xor_sync(0xffffffffu, l0, 2);
        l1 += __shfl_xor_sync(0xffffffffu, l1, 1);
        l1 += __shfl_xor_sync(0xffffffffu, l1, 2);
        float inv0 = 1.f / l0, inv1 = 1.f / l1;
        float* or0 = att + ((size_t)(b * N_TOK + q0 + mt * 16 + g)) * C_SZ + h * HDIM;
        float* or1 = or0 + (size_t)8 * C_SZ;
        #pragma unroll
        for (int nt = 0; nt < 6; nt++) {
            *(float2*)&or0[nt*8 + tig*2] =
                make_float2(o[mt][nt][0] * inv0, o[mt][nt][1] * inv0);
            *(float2*)&or1[nt*8 + tig*2] =
                make_float2(o[mt][nt][2] * inv1, o[mt][nt][3] * inv1);
        }
    }
}

// ---------------- launch --------------------------------------------------------
extern "C" void kernel_launch(void* const* d_in, const int* in_sizes, int n_in,
                              void* d_out, int out_size) {
    const float* x      = (const float*)d_in[0];
    const float* w_qkv  = (const float*)d_in[1];
    const float* w_proj = (const float*)d_in[2];
    const float* ln_w   = (const float*)d_in[3];
    const float* ln_b   = (const float*)d_in[4];
    float* out = (float*)d_out;

    float *qkv, *att, *wq1, *wp1, *uu, *vv;
    float2* stat;
    cudaGetSymbolAddress((void**)&qkv,  g_qkv);
    cudaGetSymbolAddress((void**)&att,  g_att);
    cudaGetSymbolAddress((void**)&wq1,  g_wq1);
    cudaGetSymbolAddress((void**)&wp1,  g_wp1);
    cudaGetSymbolAddress((void**)&stat, g_stat);
    cudaGetSymbolAddress((void**)&uu,   g_u);
    cudaGetSymbolAddress((void**)&vv,   g_v);

    cudaFuncSetAttribute(gemm_ln, cudaFuncAttributeMaxDynamicSharedMemorySize, LNSMEM);
    cudaFuncSetAttribute(gemm_proj, cudaFuncAttributeMaxDynamicSharedMemorySize, PSMEM);
    cudaFuncSetAttribute(attn_mma, cudaFuncAttributeMaxDynamicSharedMemorySize, ASMEM);

    // 1) fused prep: LN stats + weight prep (single launch)
    prep_kernel<<<STAT_BLKS + QKV_W + C_SZ, 256>>>(x, w_qkv, w_proj, ln_w, ln_b,
                                                   stat, wq1, wp1, uu, vv);

    // 2) fused LN + QKV GEMM: [8192 x 1152]
    gemm_ln<<<dim3(M_TOT / 128, QKV_W / 128), 256, LNSMEM>>>(x, wq1, stat, uu, vv, qkv);

    // 3) attention -> att [8192][384]
    attn_mma<<<dim3(N_TOK / 128, B_SZ * HEADS), 128, ASMEM>>>(qkv, att);

    // 4) proj GEMM + residual -> out [B][C][H][W]
    gemm_proj<<<dim3(C_SZ / 64, M_TOT / 128), 256, PSMEM>>>(wp1, att, out, x);
}

// round 16
// speedup vs baseline: 1.3329x; 1.0320x over previous
#include <cuda_runtime.h>
#include <cstdint>
#include <math.h>

#define B_SZ 8
#define C_SZ 384
#define N_TOK 1024
#define M_TOT (B_SZ * N_TOK)      // 8192
#define HEADS 8
#define HDIM 48
#define QKV_W (3 * C_SZ)          // 1152
#define STAT_BLKS (M_TOT / 64)    // 128

// ---------------- scratch ------------------------------------------------------
__device__ float g_qkv[M_TOT * QKV_W];   // [8192][1152] tf32
__device__ float g_att[M_TOT * C_SZ];    // [8192][384] attention out (fp32)
__device__ float g_wq1[QKV_W * C_SZ];    // tf32 (w_qkv * ln_w) [1152][384]
__device__ float g_wp1[C_SZ * C_SZ];     // tf32 w_proj [384][384]
__device__ float2 g_stat[M_TOT];         // per-token {r, r*mu}
__device__ float g_u[QKV_W];             // sum_k lnw_k * Wq[n][k]
__device__ float g_v[QKV_W];             // sum_k lnb_k * Wq[n][k]

// ---------------- helpers ------------------------------------------------------
__device__ __forceinline__ float fast_exp2(float x) {
    float y; asm("ex2.approx.ftz.f32 %0, %1;" : "=f"(y) : "f"(x)); return y;
}
__device__ __forceinline__ float tf32r(float x) {
    uint32_t u; asm("cvt.rna.tf32.f32 %0, %1;" : "=r"(u) : "f"(x));
    return __uint_as_float(u);
}
__device__ __forceinline__ uint32_t smem_u32(const void* p) {
    uint32_t a;
    asm("{ .reg .u64 t; cvta.to.shared.u64 t, %1; cvt.u32.u64 %0, t; }" : "=r"(a) : "l"(p));
    return a;
}
__device__ __forceinline__ void cp16(uint32_t dst, const void* src) {
    asm volatile("cp.async.cg.shared.global [%0], [%1], 16;" :: "r"(dst), "l"(src) : "memory");
}
#define CP_COMMIT() asm volatile("cp.async.commit_group;" ::: "memory")

__device__ __forceinline__ void mma_tf32(float* c, const uint32_t* a, const uint32_t* b) {
    asm volatile(
        "mma.sync.aligned.m16n8k8.row.col.f32.tf32.tf32.f32 "
        "{%0,%1,%2,%3}, {%4,%5,%6,%7}, {%8,%9}, {%0,%1,%2,%3};"
        : "+f"(c[0]), "+f"(c[1]), "+f"(c[2]), "+f"(c[3])
        : "r"(a[0]), "r"(a[1]), "r"(a[2]), "r"(a[3]), "r"(b[0]), "r"(b[1]));
}

// ---------------- fused prep: LN stats + weight prep in one launch --------------
__global__ __launch_bounds__(256) void prep_kernel(
    const float* __restrict__ x,
    const float* __restrict__ wq, const float* __restrict__ wp,
    const float* __restrict__ lnw, const float* __restrict__ lnb,
    float2* __restrict__ stat,
    float* __restrict__ wq1, float* __restrict__ wp1,
    float* __restrict__ u, float* __restrict__ v) {
    __shared__ float sred[4][64];
    __shared__ float sred2[4][64];
    int blk = blockIdx.x;
    int t = threadIdx.x;

    if (blk < STAT_BLKS) {
        int part = t >> 6;
        int tok = t & 63;
        int m = blk * 64 + tok;
        int b = m >> 10, n = m & 1023;
        const float* xb = x + ((size_t)b * C_SZ + part * 96) * N_TOK + n;
        float s = 0.f, s2 = 0.f;
        #pragma unroll 8
        for (int c = 0; c < 96; c++) {
            float vv2 = xb[(size_t)c * N_TOK];
            s += vv2; s2 += vv2 * vv2;
        }
        sred[part][tok] = s; sred2[part][tok] = s2;
        __syncthreads();
        if (part == 0) {
            s  = sred[0][tok] + sred[1][tok] + sred[2][tok] + sred[3][tok];
            s2 = sred2[0][tok] + sred2[1][tok] + sred2[2][tok] + sred2[3][tok];
            const float rC = 1.0f / C_SZ;
            float mu = s * rC;
            float var = s2 * rC - mu * mu;
            float r = rsqrtf(var + 1e-6f);
            stat[m] = make_float2(r, r * mu);
        }
    } else if (blk < STAT_BLKS + QKV_W) {
        int n = blk - STAT_BLKS;
        const float* row = wq + (size_t)n * C_SZ;
        float su = 0.f, sv = 0.f;
        for (int k = t; k < C_SZ; k += 256) {
            float pw = tf32r(row[k] * lnw[k]);
            wq1[(size_t)n * C_SZ + k] = pw;
            su += pw;
            sv += row[k] * lnb[k];
        }
        #pragma unroll
        for (int o = 16; o; o >>= 1) {
            su += __shfl_xor_sync(0xffffffffu, su, o);
            sv += __shfl_xor_sync(0xffffffffu, sv, o);
        }
        if ((t & 31) == 0) { sred[0][(t >> 5) * 2] = su; sred[0][(t >> 5) * 2 + 1] = sv; }
        __syncthreads();
        if (t == 0) {
            float tu = 0.f, tv = 0.f;
            #pragma unroll
            for (int w = 0; w < 8; w++) { tu += sred[0][w * 2]; tv += sred[0][w * 2 + 1]; }
            u[n] = tu; v[n] = tv;
        }
    } else {
        int m = blk - STAT_BLKS - QKV_W;
        for (int k = t; k < C_SZ; k += 256)
            wp1[(size_t)m * C_SZ + k] = tf32r(wp[(size_t)m * C_SZ + k]);
    }
}

// ---------------- fused LN + QKV GEMM (BK=32, 12 stages, 3-buffer ring) ----------
#define LBK 32
#define LNA_ST 136
#define LNA_FL (LBK * LNA_ST)         // 4352 floats
#define LNB_ST 36
#define LNB_FL (128 * LNB_ST)         // 4608 floats
#define LNSTG (LNA_FL + LNB_FL)       // 8960 floats
#define LNSMEM (3 * LNSTG * 4)        // 107520 B

__global__ __launch_bounds__(256, 2) void gemm_ln(
    const float* __restrict__ x, const float* __restrict__ Bw,
    const float2* __restrict__ stat, const float* __restrict__ uv_u,
    const float* __restrict__ uv_v, float* __restrict__ qkv) {
    extern __shared__ float sm[];
    const uint32_t usm = smem_u32(sm);
    const int tid = threadIdx.x;
    const int wid = tid >> 5, lane = tid & 31;
    const int g = lane >> 2, tig = lane & 3;
    const int m0 = blockIdx.x * 128, n0 = blockIdx.y * 128;
    const int bb = m0 >> 10, nt0 = m0 & 1023;
    const int warp_m = (wid & 3) * 32, warp_n = (wid >> 2) * 64;
    const int NSTG = C_SZ / LBK;    // 12

    float acc[2][8][4];
    #pragma unroll
    for (int i = 0; i < 2; i++)
        #pragma unroll
        for (int j = 0; j < 8; j++)
            #pragma unroll
            for (int e = 0; e < 4; e++) acc[i][j][e] = 0.f;

    auto issue = [&](int s) {
        int k0 = s * LBK;
        int buf = s % 3;
        uint32_t base = usm + (uint32_t)buf * (LNSTG * 4);
        // A: 32 k-rows x 128 m-floats = 1024 cp16; coalesced along m
        #pragma unroll
        for (int i = 0; i < 4; i++) {
            int id = tid + i * 256;
            int kr = id >> 5;
            int mc = (id & 31) * 4;
            cp16(base + (uint32_t)(kr * LNA_ST + mc) * 4,
                 x + ((size_t)bb * C_SZ + k0 + kr) * N_TOK + nt0 + mc);
        }
        // B: 128 n-rows x 32 k-floats = 1024 cp16
        #pragma unroll
        for (int i = 0; i < 4; i++) {
            int id = tid + i * 256;
            int row = id >> 3;
            int c = (id & 7) * 4;
            cp16(base + (uint32_t)(LNA_FL + row * LNB_ST + c) * 4,
                 Bw + (size_t)(n0 + row) * C_SZ + k0 + c);
        }
    };

    issue(0); CP_COMMIT();
    issue(1); CP_COMMIT();

    for (int s = 0; s < NSTG; s++) {
        asm volatile("cp.async.wait_group 1;" ::: "memory");
        __syncthreads();
        if (s + 2 < NSTG) issue(s + 2);
        CP_COMMIT();

        const float* As = sm + (s % 3) * LNSTG;
        const float* Bs = As + LNA_FL;
        #pragma unroll
        for (int kk = 0; kk < LBK; kk += 8) {
            uint32_t af[2][4], bf[8][2];
            #pragma unroll
            for (int mt = 0; mt < 2; mt++) {
                int r = warp_m + mt * 16 + g;
                af[mt][0] = __float_as_uint(As[(kk + tig) * LNA_ST + r]);
                af[mt][1] = __float_as_uint(As[(kk + tig) * LNA_ST + r + 8]);
                af[mt][2] = __float_as_uint(As[(kk + tig + 4) * LNA_ST + r]);
                af[mt][3] = __float_as_uint(As[(kk + tig + 4) * LNA_ST + r + 8]);
            }
            #pragma unroll
            for (int nt = 0; nt < 8; nt++) {
                int r = warp_n + nt * 8 + g;
                bf[nt][0] = __float_as_uint(Bs[r * LNB_ST + kk + tig]);
                bf[nt][1] = __float_as_uint(Bs[r * LNB_ST + kk + tig + 4]);
            }
            #pragma unroll
            for (int mt = 0; mt < 2; mt++)
                #pragma unroll
                for (int nt = 0; nt < 8; nt++)
                    mma_tf32(acc[mt][nt], af[mt], bf[nt]);
        }
    }

    #pragma unroll
    for (int mt = 0; mt < 2; mt++) {
        int row = m0 + warp_m + mt * 16 + g;
        float2 s0 = stat[row];
        float2 s1 = stat[row + 8];
        #pragma unroll
        for (int nt = 0; nt < 8; nt++) {
            int col = n0 + warp_n + nt * 8 + tig * 2;
            float2 uu = *(const float2*)&uv_u[col];
            float2 vv = *(const float2*)&uv_v[col];
            float* c = acc[mt][nt];
            float o0 = s0.x * c[0] - s0.y * uu.x + vv.x;
            float o1 = s0.x * c[1] - s0.y * uu.y + vv.y;
            float o2 = s1.x * c[2] - s1.y * uu.x + vv.x;
            float o3 = s1.x * c[3] - s1.y * uu.y + vv.y;
            *(float2*)&qkv[(size_t)row * QKV_W + col] = make_float2(tf32r(o0), tf32r(o1));
            *(float2*)&qkv[(size_t)(row + 8) * QKV_W + col] = make_float2(tf32r(o2), tf32r(o3));
        }
    }
}

// ---------------- proj GEMM (BK=32, 12 stages, 4-buffer ring) --------------------
#define PBK 32
#define PSTR 36
#define PA_FL (64 * PSTR)             // 2304 floats
#define PB_FL (128 * PSTR)            // 4608 floats
#define PSTG (PA_FL + PB_FL)          // 6912 floats
#define PSMEM (4 * PSTG * 4)          // 110592 B

__global__ __launch_bounds__(256, 2) void gemm_proj(
    const float* __restrict__ A, const float* __restrict__ Bw,
    float* __restrict__ Cout, const float* __restrict__ resid) {
    extern __shared__ float sm[];
    const uint32_t usm = smem_u32(sm);
    const int tid = threadIdx.x;
    const int wid = tid >> 5, lane = tid & 31;
    const int g = lane >> 2, tig = lane & 3;
    const int m0 = blockIdx.x * 64, n0 = blockIdx.y * 128;
    const int warp_m = (wid & 1) * 32, warp_n = (wid >> 1) * 32;
    const int NSTG = C_SZ / PBK;      // 12

    float acc[2][4][4];
    #pragma unroll
    for (int i = 0; i < 2; i++)
        #pragma unroll
        for (int j = 0; j < 4; j++)
            #pragma unroll
            for (int e = 0; e < 4; e++) acc[i][j][e] = 0.f;

    auto issue = [&](int s) {
        int k0 = s * PBK;
        uint32_t base = usm + (uint32_t)(s & 3) * (PSTG * 4);
        #pragma unroll
        for (int i = 0; i < 2; i++) {
            int id = tid + i * 256;
            int row = id >> 3, c = (id & 7) * 4;
            cp16(base + (uint32_t)(row * PSTR + c) * 4,
                 A + (size_t)(m0 + row) * C_SZ + k0 + c);
        }
        #pragma unroll
        for (int i = 0; i < 4; i++) {
            int id = tid + i * 256;
            int row = id >> 3, c = (id & 7) * 4;
            cp16(base + (uint32_t)(PA_FL + row * PSTR + c) * 4,
                 Bw + (size_t)(n0 + row) * C_SZ + k0 + c);
        }
    };

    issue(0); CP_COMMIT();
    issue(1); CP_COMMIT();
    issue(2); CP_COMMIT();

    for (int s = 0; s < NSTG; s++) {
        asm volatile("cp.async.wait_group 2;" ::: "memory");
        __syncthreads();
        if (s + 3 < NSTG) issue(s + 3);
        CP_COMMIT();

        const float* As = sm + (s & 3) * PSTG;
        const float* Bs = As + PA_FL;
        #pragma unroll
        for (int kk = 0; kk < PBK; kk += 8) {
            uint32_t af[2][4], bf[4][2];
            #pragma unroll
            for (int mt = 0; mt < 2; mt++) {
                int r = warp_m + mt * 16 + g;
                af[mt][0] = __float_as_uint(As[(r    ) * PSTR + kk + tig]);
                af[mt][1] = __float_as_uint(As[(r + 8) * PSTR + kk + tig]);
                af[mt][2] = __float_as_uint(As[(r    ) * PSTR + kk + tig + 4]);
                af[mt][3] = __float_as_uint(As[(r + 8) * PSTR + kk + tig + 4]);
            }
            #pragma unroll
            for (int nt = 0; nt < 4; nt++) {
                int r = warp_n + nt * 8 + g;
                bf[nt][0] = __float_as_uint(Bs[r * PSTR + kk + tig]);
                bf[nt][1] = __float_as_uint(Bs[r * PSTR + kk + tig + 4]);
            }
            #pragma unroll
            for (int mt = 0; mt < 2; mt++)
                #pragma unroll
                for (int nt = 0; nt < 4; nt++)
                    mma_tf32(acc[mt][nt], af[mt], bf[nt]);
        }
    }

    #pragma unroll
    for (int mt = 0; mt < 2; mt++) {
        int row = m0 + warp_m + mt * 16 + g;
        #pragma unroll
        for (int nt = 0; nt < 4; nt++) {
            int col = n0 + warp_n + nt * 8 + tig * 2;
            int bb = col >> 10, tok = col & 1023;
            float* c = acc[mt][nt];
            size_t i0 = ((size_t)bb * C_SZ + row) * N_TOK + tok;
            size_t i1 = ((size_t)bb * C_SZ + row + 8) * N_TOK + tok;
            float2 r0 = *(const float2*)&resid[i0];
            float2 r1 = *(const float2*)&resid[i1];
            *(float2*)&Cout[i0] = make_float2(r0.x + c[0], r0.y + c[1]);
            *(float2*)&Cout[i1] = make_float2(r1.x + c[2], r1.y + c[3]);
        }
    }
}

// ---------------- tensor-core flash attention (BC=128, 2 passes per load) --------
#define BC 128
#define KSTRIDE 52
#define VSTRIDE 56
#define KST (BC * KSTRIDE)
#define VST (BC * VSTRIDE)
#define ABUF (KST + VST)
#define ASMEM (2 * ABUF * 4)     // 110592 bytes

__global__ __launch_bounds__(128, 2) void attn_mma(
    const float* __restrict__ qkv, float* __restrict__ att) {
    extern __shared__ float sm[];
    const uint32_t usm = smem_u32(sm);
    const int tid = threadIdx.x;
    const int wid = tid >> 5, lane = tid & 31;
    const int g = lane >> 2, tig = lane & 3;
    const int bh = blockIdx.y;
    const int b = bh >> 3, h = bh & 7;
    const int q0 = blockIdx.x * 128 + wid * 32;
    const float QS = 0.14433756729740643f * 1.44269504088896340f;
    const int gperm = (g >> 1) + (g & 1) * 4;    // sigma(g)

    uint32_t qa[2][6][4];
    {
        const float* Qb = qkv + ((size_t)(b * N_TOK + q0)) * QKV_W + h * HDIM;
        #pragma unroll
        for (int mt = 0; mt < 2; mt++) {
            const float* Qm = Qb + (size_t)(mt * 16) * QKV_W;
            #pragma unroll
            for (int kk = 0; kk < 6; kk++) {
                qa[mt][kk][0] = __float_as_uint(tf32r(Qm[(size_t)g * QKV_W + kk*8 + tig] * QS));
                qa[mt][kk][1] = __float_as_uint(tf32r(Qm[(size_t)(g+8) * QKV_W + kk*8 + tig] * QS));
                qa[mt][kk][2] = __float_as_uint(tf32r(Qm[(size_t)g * QKV_W + kk*8 + tig + 4] * QS));
                qa[mt][kk][3] = __float_as_uint(tf32r(Qm[(size_t)(g+8) * QKV_W + kk*8 + tig + 4] * QS));
            }
        }
    }

    float o[2][6][4];
    #pragma unroll
    for (int mt = 0; mt < 2; mt++)
        #pragma unroll
        for (int nt = 0; nt < 6; nt++)
            #pragma unroll
            for (int e = 0; e < 4; e++) o[mt][nt][e] = 0.f;
    float ps[2][2] = {{0.f, 0.f}, {0.f, 0.f}};

    auto issue = [&](int t) {
        int j0 = t * BC;
        uint32_t base = usm + (uint32_t)(t & 1) * (ABUF * 4);
        const float* kb = qkv + ((size_t)(b * N_TOK + j0)) * QKV_W + C_SZ + h * HDIM;
        const float* vb = kb + C_SZ;
        #pragma unroll
        for (int i = 0; i < 12; i++) {
            int id = tid + i * 128;
            int r = id / 12, c = (id % 12) * 4;
            cp16(base + (uint32_t)(r * KSTRIDE + c) * 4, kb + (size_t)r * QKV_W + c);
            cp16(base + (uint32_t)(KST + r * VSTRIDE + c) * 4, vb + (size_t)r * QKV_W + c);
        }
    };

    issue(0); CP_COMMIT();

    for (int t = 0; t < N_TOK / BC; t++) {
        asm volatile("cp.async.wait_group 0;" ::: "memory");
        __syncthreads();
        if (t + 1 < N_TOK / BC) issue(t + 1);
        CP_COMMIT();

        #pragma unroll
        for (int pass = 0; pass < 2; pass++) {
            const float* ks = sm + (t & 1) * ABUF + pass * 64 * KSTRIDE;
            const float* vs = sm + (t & 1) * ABUF + KST + pass * 64 * VSTRIDE;

            float sc[2][8][4];
            #pragma unroll
            for (int mt = 0; mt < 2; mt++)
                #pragma unroll
                for (int nt = 0; nt < 8; nt++)
                    #pragma unroll
                    for (int e = 0; e < 4; e++) sc[mt][nt][e] = 0.f;
            #pragma unroll
            for (int kk = 0; kk < 6; kk++) {
                #pragma unroll
                for (int nt = 0; nt < 8; nt++) {
                    uint32_t bf[2];
                    bf[0] = __float_as_uint(ks[(nt*8 + gperm) * KSTRIDE + kk*8 + tig]);
                    bf[1] = __float_as_uint(ks[(nt*8 + gperm) * KSTRIDE + kk*8 + tig + 4]);
                    mma_tf32(sc[0][nt], qa[0][kk], bf);
                    mma_tf32(sc[1][nt], qa[1][kk], bf);
                }
            }

            #pragma unroll
            for (int mt = 0; mt < 2; mt++) {
                #pragma unroll
                for (int nt = 0; nt < 8; nt++) {
                    sc[mt][nt][0] = fast_exp2(sc[mt][nt][0]);
                    sc[mt][nt][1] = fast_exp2(sc[mt][nt][1]);
                    sc[mt][nt][2] = fast_exp2(sc[mt][nt][2]);
                    sc[mt][nt][3] = fast_exp2(sc[mt][nt][3]);
                    ps[mt][0] += sc[mt][nt][0] + sc[mt][nt][1];
                    ps[mt][1] += sc[mt][nt][2] + sc[mt][nt][3];
                }
            }

            #pragma unroll
            for (int kt = 0; kt < 8; kt++) {
                uint32_t pa[2][4];
                #pragma unroll
                for (int mt = 0; mt < 2; mt++) {
                    pa[mt][0] = __float_as_uint(sc[mt][kt][0]);
                    pa[mt][1] = __float_as_uint(sc[mt][kt][2]);
                    pa[mt][2] = __float_as_uint(sc[mt][kt][1]);
                    pa[mt][3] = __float_as_uint(sc[mt][kt][3]);
                }
                #pragma unroll
                for (int nt = 0; nt < 6; nt++) {
                    uint32_t bf[2];
                    bf[0] = __float_as_uint(vs[(kt*8 + tig) * VSTRIDE + nt*8 + g]);
                    bf[1] = __float_as_uint(vs[(kt*8 + tig + 4) * VSTRIDE + nt*8 + g]);
                    mma_tf32(o[0][nt], pa[0], bf);
                    mma_tf32(o[1][nt], pa[1], bf);
                }
            }
        }
    }

    #pragma unroll
    for (int mt = 0; mt < 2; mt++) {
        float l0 = ps[mt][0], l1 = ps[mt][1];
        l0 += __shfl_xor_sync(0xffffffffu, l0, 1);
        l0 += __shfl_xor_sync(0xffffffffu, l0, 2);
        l1 += __shfl_xor_sync(0xffffffffu, l1, 1);
        l1 += __shfl_xor_sync(0xffffffffu, l1, 2);
        float inv0 = 1.f / l0, inv1 = 1.f / l1;
        float* or0 = att + ((size_t)(b * N_TOK + q0 + mt * 16 + g)) * C_SZ + h * HDIM;
        float* or1 = or0 + (size_t)8 * C_SZ;
        #pragma unroll
        for (int nt = 0; nt < 6; nt++) {
            *(float2*)&or0[nt*8 + tig*2] =
                make_float2(o[mt][nt][0] * inv0, o[mt][nt][1] * inv0);
            *(float2*)&or1[nt*8 + tig*2] =
                make_float2(o[mt][nt][2] * inv1, o[mt][nt][3] * inv1);
        }
    }
}

// ---------------- launch --------------------------------------------------------
extern "C" void kernel_launch(void* const* d_in, const int* in_sizes, int n_in,
                              void* d_out, int out_size) {
    const float* x      = (const float*)d_in[0];
    const float* w_qkv  = (const float*)d_in[1];
    const float* w_proj = (const float*)d_in[2];
    const float* ln_w   = (const float*)d_in[3];
    const float* ln_b   = (const float*)d_in[4];
    float* out = (float*)d_out;

    float *qkv, *att, *wq1, *wp1, *uu, *vv;
    float2* stat;
    cudaGetSymbolAddress((void**)&qkv,  g_qkv);
    cudaGetSymbolAddress((void**)&att,  g_att);
    cudaGetSymbolAddress((void**)&wq1,  g_wq1);
    cudaGetSymbolAddress((void**)&wp1,  g_wp1);
    cudaGetSymbolAddress((void**)&stat, g_stat);
    cudaGetSymbolAddress((void**)&uu,   g_u);
    cudaGetSymbolAddress((void**)&vv,   g_v);

    cudaFuncSetAttribute(gemm_ln, cudaFuncAttributeMaxDynamicSharedMemorySize, LNSMEM);
    cudaFuncSetAttribute(gemm_proj, cudaFuncAttributeMaxDynamicSharedMemorySize, PSMEM);
    cudaFuncSetAttribute(attn_mma, cudaFuncAttributeMaxDynamicSharedMemorySize, ASMEM);

    // 1) fused prep: LN stats + weight prep (single launch)
    prep_kernel<<<STAT_BLKS + QKV_W + C_SZ, 256>>>(x, w_qkv, w_proj, ln_w, ln_b,
                                                   stat, wq1, wp1, uu, vv);

    // 2) fused LN + QKV GEMM: [8192 x 1152]
    gemm_ln<<<dim3(M_TOT / 128, QKV_W / 128), 256, LNSMEM>>>(x, wq1, stat, uu, vv, qkv);

    // 3) attention -> att [8192][384]
    attn_mma<<<dim3(N_TOK / 128, B_SZ * HEADS), 128, ASMEM>>>(qkv, att);

    // 4) proj GEMM + residual -> out [B][C][H][W]
    gemm_proj<<<dim3(C_SZ / 64, M_TOT / 128), 256, PSMEM>>>(wp1, att, out, x);
}